// round 13
// baseline (speedup 1.0000x reference)
#include <cuda_runtime.h>
#include <cuda_bf16.h>
#include <cstdint>

#define BDIM 8
#define LDIM 2048
#define DDIM 1024
#define CH   341
#define NP   384
#define NSEG 512
#define KTOT 3072
#define NCHUNK 48           // KTOT / 64

// ---------------- device scratch ----------------
__device__ __nv_bfloat16 g_hbf[BDIM * LDIM * DDIM];
__device__ __nv_bfloat16 g_Wbf[NP * KTOT];            // [c][k*1024+d]
__device__ float          g_w2p[NP];
__device__ float          g_b1p[NP];
__device__ float          g_logits[BDIM * LDIM];
__device__ unsigned short g_seg[BDIM * LDIM];
__device__ int            g_count[BDIM * NSEG];
__device__ int            g_len[BDIM];
__device__ float          g_pe[NSEG * DDIM];
__device__ int            g_fix_cnt;
__device__ int            g_fix_list[16384];

__device__ __forceinline__ uint32_t smem_u32(const void* p) {
    uint32_t a;
    asm("{ .reg .u64 t; cvta.to.shared.u64 t, %1; cvt.u32.u64 %0, t; }" : "=r"(a) : "l"(p));
    return a;
}

// ------- fused setup: zero out, convert hidden, reorder W, PE, lengths, init --
__global__ void k_setup(const float* __restrict__ h, float* __restrict__ out, int nzero,
                        const float* __restrict__ w1, const float* __restrict__ b1,
                        const float* __restrict__ w2, const float* __restrict__ amask) {
    int idx = blockIdx.x * blockDim.x + threadIdx.x;
    if (idx < nzero) out[idx] = 0.f;
    if (idx < BDIM * LDIM * DDIM / 8) {
        const float4* src = (const float4*)h;
        uint2* dst = (uint2*)g_hbf;
        float4 a = src[2 * idx], b = src[2 * idx + 1];
        __nv_bfloat162 p0 = __floats2bfloat162_rn(a.x, a.y);
        __nv_bfloat162 p1 = __floats2bfloat162_rn(a.z, a.w);
        __nv_bfloat162 p2 = __floats2bfloat162_rn(b.x, b.y);
        __nv_bfloat162 p3 = __floats2bfloat162_rn(b.z, b.w);
        uint2 o0, o1;
        o0.x = *reinterpret_cast<uint32_t*>(&p0);
        o0.y = *reinterpret_cast<uint32_t*>(&p1);
        o1.x = *reinterpret_cast<uint32_t*>(&p2);
        o1.y = *reinterpret_cast<uint32_t*>(&p3);
        dst[2 * idx] = o0;
        dst[2 * idx + 1] = o1;
    }
    if (idx < NP * KTOT) {
        int c = idx / KTOT, r = idx % KTOT;
        int k = r >> 10, d = r & 1023;
        float v = (c < CH) ? w1[((size_t)c * 1024 + d) * 3 + k] : 0.f;
        g_Wbf[idx] = __float2bfloat16(v);
    }
    if (idx < NSEG * DDIM) {
        int s = idx >> 10, d = idx & 1023;
        float freq = expf(-logf(10000.f) * (float)(d & ~1) / 1024.f);
        float ang = (float)s * freq;
        g_pe[idx] = (d & 1) ? cosf(ang) : sinf(ang);
    }
    if (idx < NP) {
        g_w2p[idx] = (idx < CH) ? w2[idx] : 0.f;
        g_b1p[idx] = (idx < CH) ? b1[idx] : 0.f;
    }
    if (idx < BDIM * LDIM) {
        g_logits[idx] = 0.f;
        // race-free length detect: unique thread at the 1->0 transition writes
        int b = idx >> 11, p = idx & (LDIM - 1);
        float cur = amask[idx];
        if (cur > 0.5f && (p == LDIM - 1 || amask[idx + 1] <= 0.5f))
            g_len[b] = p + 1;
    }
    if (idx == 0) g_fix_cnt = 0;
}

// ---------------- conv GEMM: bf16 mma.sync, 3-stage, 2 CTA/SM + tile skip ----
__global__ __launch_bounds__(256, 2) void k_conv(const float* __restrict__ dummy) {
    extern __shared__ __align__(128) char smem[];
    const uint32_t sb = smem_u32(smem);
    const int tid  = threadIdx.x;
    const int lane = tid & 31;
    const int wid  = tid >> 5;
    const int wm   = wid >> 1;
    const int wn   = wid & 1;
    const int b    = blockIdx.z;
    const int l0   = blockIdx.x * 128;
    const int n0   = blockIdx.y * 128;

    // logits only consumed for p < len (p = l+2): skip tiles entirely past it
    if (l0 >= g_len[b] - 2) return;

    const __nv_bfloat16* hbf = g_hbf;
    const __nv_bfloat16* wbf = g_Wbf;

    auto load_stage = [&](int c, int s) {
        const int k  = c >> 4;
        const int d0 = (c & 15) * 64;
        const int kc = c * 64;
        const uint32_t abase = sb + (unsigned)s * 16384u;
        const uint32_t bbase = sb + 49152u + (unsigned)s * 16384u;
#pragma unroll
        for (int i = 0; i < 4; i++) {
            int idx = tid + i * 256;
            int r = idx >> 3, c8 = idx & 7;
            long grow = (long)b * LDIM + l0 + k + r;
            const __nv_bfloat16* src = hbf + grow * DDIM + d0 + c8 * 8;
            uint32_t dst = abase + (uint32_t)(r * 128 + ((c8 ^ (r & 7)) << 4));
            unsigned nb = (grow < (long)BDIM * LDIM) ? 16u : 0u;
            asm volatile("cp.async.cg.shared.global [%0], [%1], 16, %2;"
                         :: "r"(dst), "l"(src), "r"(nb) : "memory");
        }
#pragma unroll
        for (int i = 0; i < 4; i++) {
            int idx = tid + i * 256;
            int r = idx >> 3, c8 = idx & 7;
            const __nv_bfloat16* src = wbf + (size_t)(n0 + r) * KTOT + kc + c8 * 8;
            uint32_t dst = bbase + (uint32_t)(r * 128 + ((c8 ^ (r & 7)) << 4));
            asm volatile("cp.async.cg.shared.global [%0], [%1], 16;"
                         :: "r"(dst), "l"(src) : "memory");
        }
        asm volatile("cp.async.commit_group;" ::: "memory");
    };

    float acc[2][8][4];
#pragma unroll
    for (int i = 0; i < 2; i++)
#pragma unroll
        for (int j = 0; j < 8; j++)
#pragma unroll
            for (int e = 0; e < 4; e++) acc[i][j][e] = 0.f;

    load_stage(0, 0);
    load_stage(1, 1);

    for (int c = 0; c < NCHUNK; c++) {
        const int s = c % 3;
        if (c + 2 < NCHUNK) {
            load_stage(c + 2, (c + 2) % 3);
            asm volatile("cp.async.wait_group 2;" ::: "memory");
        } else {
            asm volatile("cp.async.wait_group 0;" ::: "memory");
        }
        __syncthreads();

        const uint32_t abase = sb + (unsigned)s * 16384u;
        const uint32_t bbase = sb + 49152u + (unsigned)s * 16384u;

#pragma unroll
        for (int kk = 0; kk < 4; kk++) {
            uint32_t af[2][4];
#pragma unroll
            for (int i = 0; i < 2; i++) {
                int row = wm * 32 + i * 16 + (lane & 15);
                int chk = kk * 2 + (lane >> 4);
                uint32_t addr = abase + (uint32_t)(row * 128 + ((chk ^ (row & 7)) << 4));
                asm volatile(
                    "ldmatrix.sync.aligned.m8n8.x4.shared.b16 {%0,%1,%2,%3}, [%4];"
                    : "=r"(af[i][0]), "=r"(af[i][1]), "=r"(af[i][2]), "=r"(af[i][3])
                    : "r"(addr));
            }
            uint32_t bf[8][2];
#pragma unroll
            for (int jp = 0; jp < 4; jp++) {
                int grp = lane >> 3;
                int nrow = wn * 64 + jp * 16 + (grp >> 1) * 8 + (lane & 7);
                int chk  = kk * 2 + (grp & 1);
                uint32_t addr = bbase + (uint32_t)(nrow * 128 + ((chk ^ (nrow & 7)) << 4));
                asm volatile(
                    "ldmatrix.sync.aligned.m8n8.x4.shared.b16 {%0,%1,%2,%3}, [%4];"
                    : "=r"(bf[jp * 2][0]), "=r"(bf[jp * 2][1]),
                      "=r"(bf[jp * 2 + 1][0]), "=r"(bf[jp * 2 + 1][1])
                    : "r"(addr));
            }
#pragma unroll
            for (int i = 0; i < 2; i++)
#pragma unroll
                for (int j = 0; j < 8; j++) {
                    asm volatile(
                        "mma.sync.aligned.m16n8k16.row.col.f32.bf16.bf16.f32 "
                        "{%0,%1,%2,%3}, {%4,%5,%6,%7}, {%8,%9}, {%0,%1,%2,%3};"
                        : "+f"(acc[i][j][0]), "+f"(acc[i][j][1]),
                          "+f"(acc[i][j][2]), "+f"(acc[i][j][3])
                        : "r"(af[i][0]), "r"(af[i][1]), "r"(af[i][2]), "r"(af[i][3]),
                          "r"(bf[j][0]), "r"(bf[j][1]));
                }
        }
        __syncthreads();
    }

    float* red = (float*)smem;
    if (tid < 128) red[tid] = 0.f;
    __syncthreads();

    const int cbase = n0 + wn * 64 + (lane & 3) * 2;
#pragma unroll
    for (int i = 0; i < 2; i++) {
#pragma unroll
        for (int h = 0; h < 2; h++) {
            float s = 0.f;
#pragma unroll
            for (int j = 0; j < 8; j++) {
                int cc = cbase + j * 8;
                float v0 = acc[i][j][h * 2 + 0];
                float v1 = acc[i][j][h * 2 + 1];
                s += fmaxf(v0 + g_b1p[cc], 0.f) * g_w2p[cc];
                s += fmaxf(v1 + g_b1p[cc + 1], 0.f) * g_w2p[cc + 1];
            }
            int row = wm * 32 + i * 16 + h * 8 + (lane >> 2);
            atomicAdd(&red[row], s);
        }
    }
    __syncthreads();
    if (tid < 128) {
        int l = l0 + tid;
        if (l < LDIM - 2) atomicAdd(&g_logits[b * LDIM + l + 2], red[tid]);
    }
}

// ---------------- add b2, flag near-zero logits ----------------
__global__ void k_flag(const float* __restrict__ b2) {
    int idx = blockIdx.x * blockDim.x + threadIdx.x;
    if (idx < BDIM * (LDIM - 2)) {
        int b = idx / (LDIM - 2), l = idx % (LDIM - 2), p = l + 2;
        float v = g_logits[b * LDIM + p] + b2[0];
        g_logits[b * LDIM + p] = v;
        if (fabsf(v) < 0.3f && p < g_len[b]) {
            int i = atomicAdd(&g_fix_cnt, 1);
            if (i < 16384) g_fix_list[i] = (b << 16) | p;
        }
    }
}

// ---------------- fp32 recompute of flagged logits (ILP chains) --------------
__global__ void k_fix(const float* __restrict__ hidden, const float* __restrict__ w1,
                      const float* __restrict__ b1, const float* __restrict__ w2,
                      const float* __restrict__ b2) {
    __shared__ float sred[256];
    int n = g_fix_cnt;
    if (n > 16384) n = 16384;
    for (int it = blockIdx.x; it < n; it += gridDim.x) {
        int e = g_fix_list[it];
        int b = e >> 16, p = e & 0xffff, l = p - 2;
        const float* hb = hidden + ((size_t)b * LDIM + l) * DDIM;
        float s = 0.f;
        for (int c = threadIdx.x; c < CH; c += 256) {
            float a0 = 0.f, a1 = 0.f, a2 = 0.f;
            const float* wc = w1 + (size_t)c * 3072;
#pragma unroll 4
            for (int d = 0; d < 1024; d++) {
                a0 += hb[d] * wc[d * 3 + 0];
                a1 += hb[1024 + d] * wc[d * 3 + 1];
                a2 += hb[2048 + d] * wc[d * 3 + 2];
            }
            s += fmaxf(a0 + a1 + a2 + b1[c], 0.f) * w2[c];
        }
        sred[threadIdx.x] = s;
        __syncthreads();
        for (int o = 128; o > 0; o >>= 1) {
            if (threadIdx.x < o) sred[threadIdx.x] += sred[threadIdx.x + o];
            __syncthreads();
        }
        if (threadIdx.x == 0) g_logits[b * LDIM + p] = sred[0] + b2[0];
        __syncthreads();
    }
}

// ---------------- per-batch scan (shuffle-based, uses g_len) -----------------
__global__ void k_scan(float* __restrict__ out_short, float* __restrict__ out_scalars) {
    const int b = blockIdx.x;
    const int tid = threadIdx.x;
    const int lane = tid & 31;
    const int w = tid >> 5;
    __shared__ unsigned char sh_hard[LDIM];
    __shared__ int sh_warp[8];
    __shared__ int sh_count[NSEG];

    const int len = g_len[b];

    for (int p = tid; p < LDIM; p += 256) {
        int bit = (p >= 2 && p < len && g_logits[b * LDIM + p] > 0.f) ? 1 : 0;
        sh_hard[p] = (unsigned char)bit;
    }
    __syncthreads();
    if (tid == 0 && len < LDIM) sh_hard[len - 1] = 1;
    for (int s = tid; s < NSEG; s += 256) sh_count[s] = 0;
    __syncthreads();

    const int base = tid * 8;
    int t = 0;
    for (int q = 0; q < 8; q++) t += sh_hard[base + q];

    // inclusive scan over 256 threads via shuffles
    int v = t;
#pragma unroll
    for (int o = 1; o < 32; o <<= 1) {
        int u = __shfl_up_sync(0xffffffffu, v, o);
        if (lane >= o) v += u;
    }
    if (lane == 31) sh_warp[w] = v;
    __syncthreads();
    if (w == 0 && lane < 8) {
        int x = sh_warp[lane];
#pragma unroll
        for (int o = 1; o < 8; o <<= 1) {
            int u = __shfl_up_sync(0xffu, x, o);
            if (lane >= o) x += u;
        }
        sh_warp[lane] = x;
    }
    __syncthreads();
    const int incl = v + (w > 0 ? sh_warp[w - 1] : 0);
    const int nb = sh_warp[7];

    int run = incl - t;   // exclusive prefix
    for (int q = 0; q < 8; q++) {
        int p = base + q;
        g_seg[b * LDIM + p] = (unsigned short)run;
        if (p < len && run < NSEG) atomicAdd(&sh_count[run], 1);
        run += sh_hard[p];
    }
    __syncthreads();
    for (int s = tid; s < NSEG; s += 256) g_count[b * NSEG + s] = sh_count[s];
    for (int s = tid; s < NSEG; s += 256) out_short[b * NSEG + s] = (s < nb) ? 1.f : 0.f;
    if (tid == 0) {
        atomicAdd(&out_scalars[0], (float)nb);
        atomicAdd(&out_scalars[1], (float)len);
    }
}

// ---------------- segment-sum pooling (balanced) ----------------
__global__ __launch_bounds__(256) void k_pool(const float* __restrict__ hidden,
                                              float* __restrict__ pooled) {
    const int b = blockIdx.y;
    const int c0 = blockIdx.x * 128;
    const int tid = threadIdx.x;
    __shared__ unsigned short sseg[128];
    const int len = g_len[b];
    if (c0 >= len) return;
    if (tid < 128) sseg[tid] = g_seg[b * LDIM + c0 + tid];
    __syncthreads();

    const int d = tid * 4;
    const float* hb = hidden + ((size_t)b * LDIM + c0) * DDIM + d;
    float4 acc = make_float4(0.f, 0.f, 0.f, 0.f);
    int cur = sseg[0];
    const int lim = min(128, len - c0);
    for (int li = 0; li < lim; li++) {
        int s = sseg[li];
        if (s != cur) {
            if (cur < NSEG) {
                float* pp = pooled + ((size_t)b * NSEG + cur) * DDIM + d;
                atomicAdd(pp + 0, acc.x); atomicAdd(pp + 1, acc.y);
                atomicAdd(pp + 2, acc.z); atomicAdd(pp + 3, acc.w);
            }
            acc = make_float4(0.f, 0.f, 0.f, 0.f);
            cur = s;
        }
        float4 v = *(const float4*)(hb + (size_t)li * DDIM);
        acc.x += v.x; acc.y += v.y; acc.z += v.z; acc.w += v.w;
    }
    if (cur < NSEG) {
        float* pp = pooled + ((size_t)b * NSEG + cur) * DDIM + d;
        atomicAdd(pp + 0, acc.x); atomicAdd(pp + 1, acc.y);
        atomicAdd(pp + 2, acc.z); atomicAdd(pp + 3, acc.w);
    }
}

// ---------------- finalize: mean + PE ----------------
__global__ void k_final(float* __restrict__ out) {
    int idx = blockIdx.x * blockDim.x + threadIdx.x;
    if (idx < BDIM * NSEG * DDIM) {
        int sd = idx & (NSEG * DDIM - 1);
        int s = (idx >> 10) & (NSEG - 1);
        int b = idx >> 19;
        int cnt = g_count[b * NSEG + s];
        out[idx] = out[idx] / ((float)cnt + 1e-9f) + g_pe[sd];
    }
}

// ---------------- launch ----------------
extern "C" void kernel_launch(void* const* d_in, const int* in_sizes, int n_in,
                              void* d_out, int out_size) {
    const float* hidden = (const float*)d_in[0];
    const float* amask  = (const float*)d_in[1];
    const float* w1     = (const float*)d_in[2];
    const float* b1     = (const float*)d_in[3];
    const float* w2     = (const float*)d_in[4];
    const float* b2     = (const float*)d_in[5];
    float* out = (float*)d_out;

    const int pooled_n = BDIM * NSEG * DDIM;
    float* out_scalars = out + (out_size - BDIM * NSEG - 2);
    float* out_short   = out + (out_size - BDIM * NSEG);

    const int smem_bytes = 98304;   // 3 stages x 32KB
    cudaFuncSetAttribute(k_conv, cudaFuncAttributeMaxDynamicSharedMemorySize, smem_bytes);

    k_setup<<<(pooled_n + 2 + 255) / 256, 256>>>(hidden, out, pooled_n + 2, w1, b1, w2, amask);
    k_conv<<<dim3(16, 3, BDIM), 256, smem_bytes>>>(nullptr);
    k_flag<<<(BDIM * (LDIM - 2) + 255) / 256, 256>>>(b2);
    k_fix<<<64, 256>>>(hidden, w1, b1, w2, b2);
    k_scan<<<BDIM, 256>>>(out_short, out_scalars);
    k_pool<<<dim3(16, BDIM), 256>>>(hidden, out);
    k_final<<<(pooled_n + 255) / 256, 256>>>(out);
}

// round 14
// speedup vs baseline: 1.3403x; 1.3403x over previous
#include <cuda_runtime.h>
#include <cuda_bf16.h>
#include <cstdint>

#define BDIM 8
#define LDIM 2048
#define DDIM 1024
#define CH   341
#define NP   384
#define NSEG 512
#define KTOT 3072
#define NCHUNK 48           // KTOT / 64

// ---------------- device scratch ----------------
__device__ __nv_bfloat16 g_hbf[BDIM * LDIM * DDIM];
__device__ __nv_bfloat16 g_Wbf[NP * KTOT];            // [c][k*1024+d]
__device__ float          g_w2p[NP];
__device__ float          g_b1p[NP];
__device__ float          g_logits[BDIM * LDIM];
__device__ unsigned short g_seg[BDIM * LDIM];
__device__ int            g_count[BDIM * NSEG];
__device__ int            g_len[BDIM];
__device__ float          g_pe[NSEG * DDIM];
__device__ int            g_fix_cnt;
__device__ int            g_fix_list[16384];

__device__ __forceinline__ uint32_t smem_u32(const void* p) {
    uint32_t a;
    asm("{ .reg .u64 t; cvta.to.shared.u64 t, %1; cvt.u32.u64 %0, t; }" : "=r"(a) : "l"(p));
    return a;
}

// ------- fused setup: zero out region, convert hidden, reorder W, PE, init ----
__global__ void k_setup(const float* __restrict__ h, float* __restrict__ out, int nzero,
                        const float* __restrict__ w1, const float* __restrict__ b1,
                        const float* __restrict__ w2) {
    int idx = blockIdx.x * blockDim.x + threadIdx.x;
    if (idx < nzero) out[idx] = 0.f;
    if (idx < BDIM * LDIM * DDIM / 8) {
        const float4* src = (const float4*)h;
        uint2* dst = (uint2*)g_hbf;
        float4 a = src[2 * idx], b = src[2 * idx + 1];
        __nv_bfloat162 p0 = __floats2bfloat162_rn(a.x, a.y);
        __nv_bfloat162 p1 = __floats2bfloat162_rn(a.z, a.w);
        __nv_bfloat162 p2 = __floats2bfloat162_rn(b.x, b.y);
        __nv_bfloat162 p3 = __floats2bfloat162_rn(b.z, b.w);
        uint2 o0, o1;
        o0.x = *reinterpret_cast<uint32_t*>(&p0);
        o0.y = *reinterpret_cast<uint32_t*>(&p1);
        o1.x = *reinterpret_cast<uint32_t*>(&p2);
        o1.y = *reinterpret_cast<uint32_t*>(&p3);
        dst[2 * idx] = o0;
        dst[2 * idx + 1] = o1;
    }
    if (idx < NP * KTOT) {
        int c = idx / KTOT, r = idx % KTOT;
        int k = r >> 10, d = r & 1023;
        float v = (c < CH) ? w1[((size_t)c * 1024 + d) * 3 + k] : 0.f;
        g_Wbf[idx] = __float2bfloat16(v);
    }
    if (idx < NSEG * DDIM) {
        int s = idx >> 10, d = idx & 1023;
        float freq = expf(-logf(10000.f) * (float)(d & ~1) / 1024.f);
        float ang = (float)s * freq;
        g_pe[idx] = (d & 1) ? cosf(ang) : sinf(ang);
    }
    if (idx < NP) {
        g_w2p[idx] = (idx < CH) ? w2[idx] : 0.f;
        g_b1p[idx] = (idx < CH) ? b1[idx] : 0.f;
    }
    if (idx < BDIM * LDIM) g_logits[idx] = 0.f;
    if (idx == 0) g_fix_cnt = 0;
}

// ---------------- conv GEMM: bf16 mma.sync, 3-stage, 2 CTA/SM ----------------
// Templated on JF = N-fragments per warp (warp tile 32 x 8*JF, CTA N = 16*JF).
// JF=8: CTA N=128 (tiles y=0,1).  JF=6: CTA N=96 (tile at channel 256, covers
// all remaining real channels; 352..383 are zero-padded and contribute 0).
template <int JF>
__global__ __launch_bounds__(256, 2) void k_conv(int n0base) {
    constexpr int BROWS  = 16 * JF;            // B rows per CTA
    constexpr int BBYTES = BROWS * 128;        // per-stage B bytes
    extern __shared__ __align__(128) char smem[];
    const uint32_t sb = smem_u32(smem);
    const int tid  = threadIdx.x;
    const int lane = tid & 31;
    const int wid  = tid >> 5;
    const int wm   = wid >> 1;
    const int wn   = wid & 1;
    const int b    = blockIdx.z;
    const int l0   = blockIdx.x * 128;
    const int n0   = n0base + blockIdx.y * 128;

    const __nv_bfloat16* hbf = g_hbf;
    const __nv_bfloat16* wbf = g_Wbf;

    auto load_stage = [&](int c, int s) {
        const int k  = c >> 4;
        const int d0 = (c & 15) * 64;
        const int kc = c * 64;
        const uint32_t abase = sb + (unsigned)s * 16384u;
        const uint32_t bbase = sb + 49152u + (unsigned)s * (unsigned)BBYTES;
#pragma unroll
        for (int i = 0; i < 4; i++) {
            int idx = tid + i * 256;
            int r = idx >> 3, c8 = idx & 7;
            long grow = (long)b * LDIM + l0 + k + r;
            const __nv_bfloat16* src = hbf + grow * DDIM + d0 + c8 * 8;
            uint32_t dst = abase + (uint32_t)(r * 128 + ((c8 ^ (r & 7)) << 4));
            unsigned nb = (grow < (long)BDIM * LDIM) ? 16u : 0u;
            asm volatile("cp.async.cg.shared.global [%0], [%1], 16, %2;"
                         :: "r"(dst), "l"(src), "r"(nb) : "memory");
        }
#pragma unroll
        for (int i = 0; i < BROWS / 32; i++) {
            int idx = tid + i * 256;
            int r = idx >> 3, c8 = idx & 7;
            const __nv_bfloat16* src = wbf + (size_t)(n0 + r) * KTOT + kc + c8 * 8;
            uint32_t dst = bbase + (uint32_t)(r * 128 + ((c8 ^ (r & 7)) << 4));
            asm volatile("cp.async.cg.shared.global [%0], [%1], 16;"
                         :: "r"(dst), "l"(src) : "memory");
        }
        asm volatile("cp.async.commit_group;" ::: "memory");
    };

    float acc[2][JF][4];
#pragma unroll
    for (int i = 0; i < 2; i++)
#pragma unroll
        for (int j = 0; j < JF; j++)
#pragma unroll
            for (int e = 0; e < 4; e++) acc[i][j][e] = 0.f;

    load_stage(0, 0);
    load_stage(1, 1);

    for (int c = 0; c < NCHUNK; c++) {
        const int s = c % 3;
        if (c + 2 < NCHUNK) {
            load_stage(c + 2, (c + 2) % 3);
            asm volatile("cp.async.wait_group 2;" ::: "memory");
        } else {
            asm volatile("cp.async.wait_group 0;" ::: "memory");
        }
        __syncthreads();

        const uint32_t abase = sb + (unsigned)s * 16384u;
        const uint32_t bbase = sb + 49152u + (unsigned)s * (unsigned)BBYTES;

#pragma unroll
        for (int kk = 0; kk < 4; kk++) {
            uint32_t af[2][4];
#pragma unroll
            for (int i = 0; i < 2; i++) {
                int row = wm * 32 + i * 16 + (lane & 15);
                int chk = kk * 2 + (lane >> 4);
                uint32_t addr = abase + (uint32_t)(row * 128 + ((chk ^ (row & 7)) << 4));
                asm volatile(
                    "ldmatrix.sync.aligned.m8n8.x4.shared.b16 {%0,%1,%2,%3}, [%4];"
                    : "=r"(af[i][0]), "=r"(af[i][1]), "=r"(af[i][2]), "=r"(af[i][3])
                    : "r"(addr));
            }
            uint32_t bf[JF][2];
#pragma unroll
            for (int jp = 0; jp < JF / 2; jp++) {
                int grp = lane >> 3;
                int nrow = wn * (JF * 8) + jp * 16 + (grp >> 1) * 8 + (lane & 7);
                int chk  = kk * 2 + (grp & 1);
                uint32_t addr = bbase + (uint32_t)(nrow * 128 + ((chk ^ (nrow & 7)) << 4));
                asm volatile(
                    "ldmatrix.sync.aligned.m8n8.x4.shared.b16 {%0,%1,%2,%3}, [%4];"
                    : "=r"(bf[jp * 2][0]), "=r"(bf[jp * 2][1]),
                      "=r"(bf[jp * 2 + 1][0]), "=r"(bf[jp * 2 + 1][1])
                    : "r"(addr));
            }
#pragma unroll
            for (int i = 0; i < 2; i++)
#pragma unroll
                for (int j = 0; j < JF; j++) {
                    asm volatile(
                        "mma.sync.aligned.m16n8k16.row.col.f32.bf16.bf16.f32 "
                        "{%0,%1,%2,%3}, {%4,%5,%6,%7}, {%8,%9}, {%0,%1,%2,%3};"
                        : "+f"(acc[i][j][0]), "+f"(acc[i][j][1]),
                          "+f"(acc[i][j][2]), "+f"(acc[i][j][3])
                        : "r"(af[i][0]), "r"(af[i][1]), "r"(af[i][2]), "r"(af[i][3]),
                          "r"(bf[j][0]), "r"(bf[j][1]));
                }
        }
        __syncthreads();
    }

    float* red = (float*)smem;
    if (tid < 128) red[tid] = 0.f;
    __syncthreads();

    const int cbase = n0 + wn * (JF * 8) + (lane & 3) * 2;
#pragma unroll
    for (int i = 0; i < 2; i++) {
#pragma unroll
        for (int h = 0; h < 2; h++) {
            float s = 0.f;
#pragma unroll
            for (int j = 0; j < JF; j++) {
                int cc = cbase + j * 8;
                float v0 = acc[i][j][h * 2 + 0];
                float v1 = acc[i][j][h * 2 + 1];
                s += fmaxf(v0 + g_b1p[cc], 0.f) * g_w2p[cc];
                s += fmaxf(v1 + g_b1p[cc + 1], 0.f) * g_w2p[cc + 1];
            }
            int row = wm * 32 + i * 16 + h * 8 + (lane >> 2);
            atomicAdd(&red[row], s);
        }
    }
    __syncthreads();
    if (tid < 128) {
        int l = l0 + tid;
        if (l < LDIM - 2) atomicAdd(&g_logits[b * LDIM + l + 2], red[tid]);
    }
}

// ---------------- add b2, flag near-zero logits ----------------
__global__ void k_flag(const float* __restrict__ b2) {
    int idx = blockIdx.x * blockDim.x + threadIdx.x;
    if (idx < BDIM * (LDIM - 2)) {
        int b = idx / (LDIM - 2), l = idx % (LDIM - 2), p = l + 2;
        float v = g_logits[b * LDIM + p] + b2[0];
        g_logits[b * LDIM + p] = v;
        if (fabsf(v) < 0.3f) {
            int i = atomicAdd(&g_fix_cnt, 1);
            if (i < 16384) g_fix_list[i] = (b << 16) | p;
        }
    }
}

// ---------------- fp32 recompute of flagged logits (ILP chains) --------------
__global__ void k_fix(const float* __restrict__ hidden, const float* __restrict__ w1,
                      const float* __restrict__ b1, const float* __restrict__ w2,
                      const float* __restrict__ b2) {
    __shared__ float sred[256];
    int n = g_fix_cnt;
    if (n > 16384) n = 16384;
    for (int it = blockIdx.x; it < n; it += gridDim.x) {
        int e = g_fix_list[it];
        int b = e >> 16, p = e & 0xffff, l = p - 2;
        const float* hb = hidden + ((size_t)b * LDIM + l) * DDIM;
        float s = 0.f;
        for (int c = threadIdx.x; c < CH; c += 256) {
            float a0 = 0.f, a1 = 0.f, a2 = 0.f;
            const float* wc = w1 + (size_t)c * 3072;
#pragma unroll 4
            for (int d = 0; d < 1024; d++) {
                a0 += hb[d] * wc[d * 3 + 0];
                a1 += hb[1024 + d] * wc[d * 3 + 1];
                a2 += hb[2048 + d] * wc[d * 3 + 2];
            }
            s += fmaxf(a0 + a1 + a2 + b1[c], 0.f) * w2[c];
        }
        sred[threadIdx.x] = s;
        __syncthreads();
        for (int o = 128; o > 0; o >>= 1) {
            if (threadIdx.x < o) sred[threadIdx.x] += sred[threadIdx.x + o];
            __syncthreads();
        }
        if (threadIdx.x == 0) g_logits[b * LDIM + p] = sred[0] + b2[0];
        __syncthreads();
    }
}

// ---------------- per-batch scan (R10-exact) ----------------
__global__ void k_scan(const float* __restrict__ mask, float* __restrict__ out_short,
                       float* __restrict__ out_scalars) {
    const int b = blockIdx.x;
    const int tid = threadIdx.x;
    __shared__ int sh_red[256];
    __shared__ unsigned char sh_hard[LDIM];
    __shared__ int sh_scan[256];
    __shared__ int sh_len;
    __shared__ int sh_count[NSEG];

    const float* mb = mask + b * LDIM;
    int ls = 0;
    for (int p = tid; p < LDIM; p += 256) ls += (mb[p] > 0.5f) ? 1 : 0;
    sh_red[tid] = ls;
    __syncthreads();
    for (int o = 128; o > 0; o >>= 1) {
        if (tid < o) sh_red[tid] += sh_red[tid + o];
        __syncthreads();
    }
    if (tid == 0) sh_len = sh_red[0];
    __syncthreads();
    const int len = sh_len;

    for (int p = tid; p < LDIM; p += 256) {
        int bit = (p >= 2 && p < len && g_logits[b * LDIM + p] > 0.f) ? 1 : 0;
        sh_hard[p] = (unsigned char)bit;
    }
    __syncthreads();
    if (tid == 0 && len < LDIM) sh_hard[len - 1] = 1;
    for (int s = tid; s < NSEG; s += 256) sh_count[s] = 0;
    __syncthreads();

    const int base = tid * 8;
    int t = 0;
    for (int q = 0; q < 8; q++) t += sh_hard[base + q];
    sh_scan[tid] = t;
    __syncthreads();
    for (int o = 1; o < 256; o <<= 1) {
        int v = sh_scan[tid];
        int u = (tid >= o) ? sh_scan[tid - o] : 0;
        __syncthreads();
        sh_scan[tid] = v + u;
        __syncthreads();
    }
    const int nb = sh_scan[255];
    int run = sh_scan[tid] - t;
    for (int q = 0; q < 8; q++) {
        int p = base + q;
        g_seg[b * LDIM + p] = (unsigned short)run;
        if (p < len && run < NSEG) atomicAdd(&sh_count[run], 1);
        run += sh_hard[p];
    }
    __syncthreads();
    for (int s = tid; s < NSEG; s += 256) g_count[b * NSEG + s] = sh_count[s];
    for (int s = tid; s < NSEG; s += 256) out_short[b * NSEG + s] = (s < nb) ? 1.f : 0.f;
    if (tid == 0) {
        g_len[b] = len;
        atomicAdd(&out_scalars[0], (float)nb);
        atomicAdd(&out_scalars[1], (float)len);
    }
}

// ---------------- segment-sum pooling (balanced, R10-exact) ------------------
__global__ __launch_bounds__(256) void k_pool(const float* __restrict__ hidden,
                                              float* __restrict__ pooled) {
    const int b = blockIdx.y;
    const int c0 = blockIdx.x * 128;
    const int tid = threadIdx.x;
    __shared__ unsigned short sseg[128];
    const int len = g_len[b];
    if (c0 >= len) return;
    if (tid < 128) sseg[tid] = g_seg[b * LDIM + c0 + tid];
    __syncthreads();

    const int d = tid * 4;
    const float* hb = hidden + ((size_t)b * LDIM + c0) * DDIM + d;
    float4 acc = make_float4(0.f, 0.f, 0.f, 0.f);
    int cur = sseg[0];
    const int lim = min(128, len - c0);
    for (int li = 0; li < lim; li++) {
        int s = sseg[li];
        if (s != cur) {
            if (cur < NSEG) {
                float* pp = pooled + ((size_t)b * NSEG + cur) * DDIM + d;
                atomicAdd(pp + 0, acc.x); atomicAdd(pp + 1, acc.y);
                atomicAdd(pp + 2, acc.z); atomicAdd(pp + 3, acc.w);
            }
            acc = make_float4(0.f, 0.f, 0.f, 0.f);
            cur = s;
        }
        float4 v = *(const float4*)(hb + (size_t)li * DDIM);
        acc.x += v.x; acc.y += v.y; acc.z += v.z; acc.w += v.w;
    }
    if (cur < NSEG) {
        float* pp = pooled + ((size_t)b * NSEG + cur) * DDIM + d;
        atomicAdd(pp + 0, acc.x); atomicAdd(pp + 1, acc.y);
        atomicAdd(pp + 2, acc.z); atomicAdd(pp + 3, acc.w);
    }
}

// ---------------- finalize: mean + PE ----------------
__global__ void k_final(float* __restrict__ out) {
    int idx = blockIdx.x * blockDim.x + threadIdx.x;
    if (idx < BDIM * NSEG * DDIM) {
        int sd = idx & (NSEG * DDIM - 1);
        int s = (idx >> 10) & (NSEG - 1);
        int b = idx >> 19;
        int cnt = g_count[b * NSEG + s];
        out[idx] = out[idx] / ((float)cnt + 1e-9f) + g_pe[sd];
    }
}

// ---------------- launch ----------------
extern "C" void kernel_launch(void* const* d_in, const int* in_sizes, int n_in,
                              void* d_out, int out_size) {
    const float* hidden = (const float*)d_in[0];
    const float* amask  = (const float*)d_in[1];
    const float* w1     = (const float*)d_in[2];
    const float* b1     = (const float*)d_in[3];
    const float* w2     = (const float*)d_in[4];
    const float* b2     = (const float*)d_in[5];
    float* out = (float*)d_out;

    const int pooled_n = BDIM * NSEG * DDIM;
    float* out_scalars = out + (out_size - BDIM * NSEG - 2);
    float* out_short   = out + (out_size - BDIM * NSEG);

    const int smem8 = 49152 + 3 * 16384;   // 98304
    const int smem6 = 49152 + 3 * 12288;   // 86016
    cudaFuncSetAttribute(k_conv<8>, cudaFuncAttributeMaxDynamicSharedMemorySize, smem8);
    cudaFuncSetAttribute(k_conv<6>, cudaFuncAttributeMaxDynamicSharedMemorySize, smem6);

    k_setup<<<(pooled_n + 2 + 255) / 256, 256>>>(hidden, out, pooled_n + 2, w1, b1, w2);
    k_conv<8><<<dim3(16, 2, BDIM), 256, smem8>>>(0);     // channels 0..255
    k_conv<6><<<dim3(16, 1, BDIM), 256, smem6>>>(256);   // channels 256..351
    k_flag<<<(BDIM * (LDIM - 2) + 255) / 256, 256>>>(b2);
    k_fix<<<64, 256>>>(hidden, w1, b1, w2, b2);
    k_scan<<<BDIM, 256>>>(amask, out_short, out_scalars);
    k_pool<<<dim3(16, BDIM), 256>>>(hidden, out);
    k_final<<<(pooled_n + 255) / 256, 256>>>(out);
}

// round 16
// speedup vs baseline: 1.4915x; 1.1128x over previous
#include <cuda_runtime.h>
#include <cuda_bf16.h>
#include <cstdint>

#define BDIM 8
#define LDIM 2048
#define DDIM 1024
#define CH   341
#define NP   384
#define NSEG 512
#define KTOT 3072
#define NCHUNK 48           // KTOT / 64

// ---------------- device scratch ----------------
__device__ __nv_bfloat16 g_hbf[BDIM * LDIM * DDIM];
__device__ __nv_bfloat16 g_Wbf[NP * KTOT];            // [c][k*1024+d]
__device__ float          g_w2p[NP];
__device__ float          g_b1p[NP];
__device__ float          g_logits[BDIM * LDIM];
__device__ unsigned short g_seg[BDIM * LDIM];
__device__ int            g_count[BDIM * NSEG];
__device__ int            g_len[BDIM];
__device__ int            g_fix_cnt;
__device__ int            g_fix_list[16384];

__device__ __forceinline__ uint32_t smem_u32(const void* p) {
    uint32_t a;
    asm("{ .reg .u64 t; cvta.to.shared.u64 t, %1; cvt.u32.u64 %0, t; }" : "=r"(a) : "l"(p));
    return a;
}

// ------- fused setup: PE into out, convert hidden, reorder W, lengths, init ---
__global__ void k_setup(const float* __restrict__ h, float* __restrict__ out,
                        float* __restrict__ out_scalars,
                        const float* __restrict__ w1, const float* __restrict__ b1,
                        const float* __restrict__ w2, const float* __restrict__ amask) {
    int idx = blockIdx.x * blockDim.x + threadIdx.x;
    // pooled output region pre-filled with PE (replaces zero-fill + k_final add)
    if (idx < BDIM * NSEG * DDIM) {
        int sd = idx & (NSEG * DDIM - 1);
        int s = sd >> 10, d = sd & 1023;
        float freq = expf(-logf(10000.f) * (float)(d & ~1) / 1024.f);
        float ang = (float)s * freq;
        out[idx] = (d & 1) ? cosf(ang) : sinf(ang);
    }
    if (idx < BDIM * LDIM * DDIM / 8) {
        const float4* src = (const float4*)h;
        uint2* dst = (uint2*)g_hbf;
        float4 a = src[2 * idx], b = src[2 * idx + 1];
        __nv_bfloat162 p0 = __floats2bfloat162_rn(a.x, a.y);
        __nv_bfloat162 p1 = __floats2bfloat162_rn(a.z, a.w);
        __nv_bfloat162 p2 = __floats2bfloat162_rn(b.x, b.y);
        __nv_bfloat162 p3 = __floats2bfloat162_rn(b.z, b.w);
        uint2 o0, o1;
        o0.x = *reinterpret_cast<uint32_t*>(&p0);
        o0.y = *reinterpret_cast<uint32_t*>(&p1);
        o1.x = *reinterpret_cast<uint32_t*>(&p2);
        o1.y = *reinterpret_cast<uint32_t*>(&p3);
        dst[2 * idx] = o0;
        dst[2 * idx + 1] = o1;
    }
    if (idx < NP * KTOT) {
        int c = idx / KTOT, r = idx % KTOT;
        int k = r >> 10, d = r & 1023;
        float v = (c < CH) ? w1[((size_t)c * 1024 + d) * 3 + k] : 0.f;
        g_Wbf[idx] = __float2bfloat16(v);
    }
    if (idx < NP) {
        g_w2p[idx] = (idx < CH) ? w2[idx] : 0.f;
        g_b1p[idx] = (idx < CH) ? b1[idx] : 0.f;
    }
    if (idx < BDIM * LDIM) {
        g_logits[idx] = 0.f;
        // race-free length detect: unique thread at the 1->0 transition writes
        int b = idx >> 11, p = idx & (LDIM - 1);
        if (amask[idx] > 0.5f && (p == LDIM - 1 || amask[idx + 1] <= 0.5f))
            g_len[b] = p + 1;
    }
    if (idx == 0) { g_fix_cnt = 0; out_scalars[0] = 0.f; out_scalars[1] = 0.f; }
}

// ---------------- conv GEMM: bf16 mma.sync, 3-stage, 2 CTA/SM (R10-exact) ----
__global__ __launch_bounds__(256, 2) void k_conv(const float* __restrict__ dummy) {
    extern __shared__ __align__(128) char smem[];
    const uint32_t sb = smem_u32(smem);
    const int tid  = threadIdx.x;
    const int lane = tid & 31;
    const int wid  = tid >> 5;
    const int wm   = wid >> 1;
    const int wn   = wid & 1;
    const int b    = blockIdx.z;
    const int l0   = blockIdx.x * 128;
    const int n0   = blockIdx.y * 128;

    const __nv_bfloat16* hbf = g_hbf;
    const __nv_bfloat16* wbf = g_Wbf;

    auto load_stage = [&](int c, int s) {
        const int k  = c >> 4;
        const int d0 = (c & 15) * 64;
        const int kc = c * 64;
        const uint32_t abase = sb + (unsigned)s * 16384u;
        const uint32_t bbase = sb + 49152u + (unsigned)s * 16384u;
#pragma unroll
        for (int i = 0; i < 4; i++) {
            int idx = tid + i * 256;
            int r = idx >> 3, c8 = idx & 7;
            long grow = (long)b * LDIM + l0 + k + r;
            const __nv_bfloat16* src = hbf + grow * DDIM + d0 + c8 * 8;
            uint32_t dst = abase + (uint32_t)(r * 128 + ((c8 ^ (r & 7)) << 4));
            unsigned nb = (grow < (long)BDIM * LDIM) ? 16u : 0u;
            asm volatile("cp.async.cg.shared.global [%0], [%1], 16, %2;"
                         :: "r"(dst), "l"(src), "r"(nb) : "memory");
        }
#pragma unroll
        for (int i = 0; i < 4; i++) {
            int idx = tid + i * 256;
            int r = idx >> 3, c8 = idx & 7;
            const __nv_bfloat16* src = wbf + (size_t)(n0 + r) * KTOT + kc + c8 * 8;
            uint32_t dst = bbase + (uint32_t)(r * 128 + ((c8 ^ (r & 7)) << 4));
            asm volatile("cp.async.cg.shared.global [%0], [%1], 16;"
                         :: "r"(dst), "l"(src) : "memory");
        }
        asm volatile("cp.async.commit_group;" ::: "memory");
    };

    float acc[2][8][4];
#pragma unroll
    for (int i = 0; i < 2; i++)
#pragma unroll
        for (int j = 0; j < 8; j++)
#pragma unroll
            for (int e = 0; e < 4; e++) acc[i][j][e] = 0.f;

    load_stage(0, 0);
    load_stage(1, 1);

    for (int c = 0; c < NCHUNK; c++) {
        const int s = c % 3;
        if (c + 2 < NCHUNK) {
            load_stage(c + 2, (c + 2) % 3);
            asm volatile("cp.async.wait_group 2;" ::: "memory");
        } else {
            asm volatile("cp.async.wait_group 0;" ::: "memory");
        }
        __syncthreads();

        const uint32_t abase = sb + (unsigned)s * 16384u;
        const uint32_t bbase = sb + 49152u + (unsigned)s * 16384u;

#pragma unroll
        for (int kk = 0; kk < 4; kk++) {
            uint32_t af[2][4];
#pragma unroll
            for (int i = 0; i < 2; i++) {
                int row = wm * 32 + i * 16 + (lane & 15);
                int chk = kk * 2 + (lane >> 4);
                uint32_t addr = abase + (uint32_t)(row * 128 + ((chk ^ (row & 7)) << 4));
                asm volatile(
                    "ldmatrix.sync.aligned.m8n8.x4.shared.b16 {%0,%1,%2,%3}, [%4];"
                    : "=r"(af[i][0]), "=r"(af[i][1]), "=r"(af[i][2]), "=r"(af[i][3])
                    : "r"(addr));
            }
            uint32_t bf[8][2];
#pragma unroll
            for (int jp = 0; jp < 4; jp++) {
                int grp = lane >> 3;
                int nrow = wn * 64 + jp * 16 + (grp >> 1) * 8 + (lane & 7);
                int chk  = kk * 2 + (grp & 1);
                uint32_t addr = bbase + (uint32_t)(nrow * 128 + ((chk ^ (nrow & 7)) << 4));
                asm volatile(
                    "ldmatrix.sync.aligned.m8n8.x4.shared.b16 {%0,%1,%2,%3}, [%4];"
                    : "=r"(bf[jp * 2][0]), "=r"(bf[jp * 2][1]),
                      "=r"(bf[jp * 2 + 1][0]), "=r"(bf[jp * 2 + 1][1])
                    : "r"(addr));
            }
#pragma unroll
            for (int i = 0; i < 2; i++)
#pragma unroll
                for (int j = 0; j < 8; j++) {
                    asm volatile(
                        "mma.sync.aligned.m16n8k16.row.col.f32.bf16.bf16.f32 "
                        "{%0,%1,%2,%3}, {%4,%5,%6,%7}, {%8,%9}, {%0,%1,%2,%3};"
                        : "+f"(acc[i][j][0]), "+f"(acc[i][j][1]),
                          "+f"(acc[i][j][2]), "+f"(acc[i][j][3])
                        : "r"(af[i][0]), "r"(af[i][1]), "r"(af[i][2]), "r"(af[i][3]),
                          "r"(bf[j][0]), "r"(bf[j][1]));
                }
        }
        __syncthreads();
    }

    float* red = (float*)smem;
    if (tid < 128) red[tid] = 0.f;
    __syncthreads();

    const int cbase = n0 + wn * 64 + (lane & 3) * 2;
#pragma unroll
    for (int i = 0; i < 2; i++) {
#pragma unroll
        for (int h = 0; h < 2; h++) {
            float s = 0.f;
#pragma unroll
            for (int j = 0; j < 8; j++) {
                int cc = cbase + j * 8;
                float v0 = acc[i][j][h * 2 + 0];
                float v1 = acc[i][j][h * 2 + 1];
                s += fmaxf(v0 + g_b1p[cc], 0.f) * g_w2p[cc];
                s += fmaxf(v1 + g_b1p[cc + 1], 0.f) * g_w2p[cc + 1];
            }
            int row = wm * 32 + i * 16 + h * 8 + (lane >> 2);
            atomicAdd(&red[row], s);
        }
    }
    __syncthreads();
    if (tid < 128) {
        int l = l0 + tid;
        if (l < LDIM - 2) atomicAdd(&g_logits[b * LDIM + l + 2], red[tid]);
    }
}

// ---------------- add b2, flag near-zero logits ----------------
__global__ void k_flag(const float* __restrict__ b2) {
    int idx = blockIdx.x * blockDim.x + threadIdx.x;
    if (idx < BDIM * (LDIM - 2)) {
        int b = idx / (LDIM - 2), l = idx % (LDIM - 2), p = l + 2;
        float v = g_logits[b * LDIM + p] + b2[0];
        g_logits[b * LDIM + p] = v;
        if (fabsf(v) < 0.3f) {
            int i = atomicAdd(&g_fix_cnt, 1);
            if (i < 16384) g_fix_list[i] = (b << 16) | p;
        }
    }
}

// ---------------- fp32 recompute of flagged logits ----------------
__global__ void k_fix(const float* __restrict__ hidden, const float* __restrict__ w1,
                      const float* __restrict__ b1, const float* __restrict__ w2,
                      const float* __restrict__ b2) {
    __shared__ float sred[256];
    int n = g_fix_cnt;
    if (n > 16384) n = 16384;
    for (int it = blockIdx.x; it < n; it += gridDim.x) {
        int e = g_fix_list[it];
        int b = e >> 16, p = e & 0xffff, l = p - 2;
        const float* hb = hidden + ((size_t)b * LDIM + l) * DDIM;
        float s = 0.f;
        for (int c = threadIdx.x; c < CH; c += 256) {
            float a0 = 0.f, a1 = 0.f, a2 = 0.f;
            const float* wc = w1 + (size_t)c * 3072;
#pragma unroll 4
            for (int d = 0; d < 1024; d++) {
                a0 += hb[d] * wc[d * 3 + 0];
                a1 += hb[1024 + d] * wc[d * 3 + 1];
                a2 += hb[2048 + d] * wc[d * 3 + 2];
            }
            s += fmaxf(a0 + a1 + a2 + b1[c], 0.f) * w2[c];
        }
        sred[threadIdx.x] = s;
        __syncthreads();
        for (int o = 128; o > 0; o >>= 1) {
            if (threadIdx.x < o) sred[threadIdx.x] += sred[threadIdx.x + o];
            __syncthreads();
        }
        if (threadIdx.x == 0) g_logits[b * LDIM + p] = sred[0] + b2[0];
        __syncthreads();
    }
}

// ---------------- per-batch scan (shuffle-based, uses g_len) -----------------
__global__ void k_scan(float* __restrict__ out_short, float* __restrict__ out_scalars) {
    const int b = blockIdx.x;
    const int tid = threadIdx.x;
    const int lane = tid & 31;
    const int w = tid >> 5;
    __shared__ unsigned char sh_hard[LDIM];
    __shared__ int sh_warp[8];
    __shared__ int sh_count[NSEG];

    const int len = g_len[b];

    for (int p = tid; p < LDIM; p += 256) {
        int bit = (p >= 2 && p < len && g_logits[b * LDIM + p] > 0.f) ? 1 : 0;
        sh_hard[p] = (unsigned char)bit;
    }
    __syncthreads();
    if (tid == 0 && len < LDIM) sh_hard[len - 1] = 1;
    for (int s = tid; s < NSEG; s += 256) sh_count[s] = 0;
    __syncthreads();

    const int base = tid * 8;
    int t = 0;
    for (int q = 0; q < 8; q++) t += sh_hard[base + q];

    int v = t;
#pragma unroll
    for (int o = 1; o < 32; o <<= 1) {
        int u = __shfl_up_sync(0xffffffffu, v, o);
        if (lane >= o) v += u;
    }
    if (lane == 31) sh_warp[w] = v;
    __syncthreads();
    if (w == 0 && lane < 8) {
        int x = sh_warp[lane];
#pragma unroll
        for (int o = 1; o < 8; o <<= 1) {
            int u = __shfl_up_sync(0xffu, x, o);
            if (lane >= o) x += u;
        }
        sh_warp[lane] = x;
    }
    __syncthreads();
    const int incl = v + (w > 0 ? sh_warp[w - 1] : 0);
    const int nb = sh_warp[7];

    int run = incl - t;
    for (int q = 0; q < 8; q++) {
        int p = base + q;
        g_seg[b * LDIM + p] = (unsigned short)run;
        if (p < len && run < NSEG) atomicAdd(&sh_count[run], 1);
        run += sh_hard[p];
    }
    __syncthreads();
    for (int s = tid; s < NSEG; s += 256) g_count[b * NSEG + s] = sh_count[s];
    for (int s = tid; s < NSEG; s += 256) out_short[b * NSEG + s] = (s < nb) ? 1.f : 0.f;
    if (tid == 0) {
        atomicAdd(&out_scalars[0], (float)nb);
        atomicAdd(&out_scalars[1], (float)len);
    }
}

// ------- segment-mean pooling: adds partial*inv(cnt) onto PE-prefilled out ---
__global__ __launch_bounds__(256) void k_pool(const float* __restrict__ hidden,
                                              float* __restrict__ pooled) {
    const int b = blockIdx.y;
    const int c0 = blockIdx.x * 128;
    const int tid = threadIdx.x;
    __shared__ unsigned short sseg[128];
    const int len = g_len[b];
    if (c0 >= len) return;
    if (tid < 128) sseg[tid] = g_seg[b * LDIM + c0 + tid];
    __syncthreads();

    const int d = tid * 4;
    const float* hb = hidden + ((size_t)b * LDIM + c0) * DDIM + d;
    float4 acc = make_float4(0.f, 0.f, 0.f, 0.f);
    int cur = sseg[0];
    const int lim = min(128, len - c0);
    for (int li = 0; li < lim; li++) {
        int s = sseg[li];
        if (s != cur) {
            if (cur < NSEG) {
                float inv = 1.f / ((float)g_count[b * NSEG + cur] + 1e-9f);
                float* pp = pooled + ((size_t)b * NSEG + cur) * DDIM + d;
                atomicAdd(pp + 0, acc.x * inv); atomicAdd(pp + 1, acc.y * inv);
                atomicAdd(pp + 2, acc.z * inv); atomicAdd(pp + 3, acc.w * inv);
            }
            acc = make_float4(0.f, 0.f, 0.f, 0.f);
            cur = s;
        }
        float4 v = *(const float4*)(hb + (size_t)li * DDIM);
        acc.x += v.x; acc.y += v.y; acc.z += v.z; acc.w += v.w;
    }
    if (cur < NSEG) {
        float inv = 1.f / ((float)g_count[b * NSEG + cur] + 1e-9f);
        float* pp = pooled + ((size_t)b * NSEG + cur) * DDIM + d;
        atomicAdd(pp + 0, acc.x * inv); atomicAdd(pp + 1, acc.y * inv);
        atomicAdd(pp + 2, acc.z * inv); atomicAdd(pp + 3, acc.w * inv);
    }
}

// ---------------- launch ----------------
extern "C" void kernel_launch(void* const* d_in, const int* in_sizes, int n_in,
                              void* d_out, int out_size) {
    const float* hidden = (const float*)d_in[0];
    const float* amask  = (const float*)d_in[1];
    const float* w1     = (const float*)d_in[2];
    const float* b1     = (const float*)d_in[3];
    const float* w2     = (const float*)d_in[4];
    const float* b2     = (const float*)d_in[5];
    float* out = (float*)d_out;

    const int pooled_n = BDIM * NSEG * DDIM;
    float* out_scalars = out + (out_size - BDIM * NSEG - 2);
    float* out_short   = out + (out_size - BDIM * NSEG);

    const int smem_bytes = 98304;   // 3 stages x 32KB
    cudaFuncSetAttribute(k_conv, cudaFuncAttributeMaxDynamicSharedMemorySize, smem_bytes);

    k_setup<<<(pooled_n + 255) / 256, 256>>>(hidden, out, out_scalars, w1, b1, w2, amask);
    k_conv<<<dim3(16, 3, BDIM), 256, smem_bytes>>>(nullptr);
    k_flag<<<(BDIM * (LDIM - 2) + 255) / 256, 256>>>(b2);
    k_fix<<<64, 256>>>(hidden, w1, b1, w2, b2);
    k_scan<<<BDIM, 256>>>(out_short, out_scalars);
    k_pool<<<dim3(16, BDIM), 256>>>(hidden, out);
}

// round 17
// speedup vs baseline: 1.7423x; 1.1681x over previous
#include <cuda_runtime.h>
#include <cuda_bf16.h>
#include <cstdint>

#define BDIM 8
#define LDIM 2048
#define DDIM 1024
#define CH   341
#define NP   384
#define NSEG 512
#define KTOT 3072
#define NCHUNK 48           // KTOT / 64

// ---------------- device scratch ----------------
__device__ __nv_bfloat16 g_hbf[BDIM * LDIM * DDIM];
__device__ __nv_bfloat16 g_Wbf[NP * KTOT];            // [c][k*1024+d]
__device__ float          g_w2p[NP];
__device__ float          g_b1p[NP];
__device__ float          g_logits[BDIM * LDIM];
__device__ unsigned short g_seg[BDIM * LDIM];
__device__ int            g_count[BDIM * NSEG];
__device__ int            g_len[BDIM];

__device__ __forceinline__ uint32_t smem_u32(const void* p) {
    uint32_t a;
    asm("{ .reg .u64 t; cvta.to.shared.u64 t, %1; cvt.u32.u64 %0, t; }" : "=r"(a) : "l"(p));
    return a;
}

// ------- fused setup: PE into out, convert hidden, reorder W, lengths, init ---
__global__ void k_setup(const float* __restrict__ h, float* __restrict__ out,
                        float* __restrict__ out_scalars,
                        const float* __restrict__ w1, const float* __restrict__ b1,
                        const float* __restrict__ w2, const float* __restrict__ amask) {
    int idx = blockIdx.x * blockDim.x + threadIdx.x;
    // pooled output region pre-filled with PE (replaces zero-fill + k_final add)
    if (idx < BDIM * NSEG * DDIM) {
        int sd = idx & (NSEG * DDIM - 1);
        int s = sd >> 10, d = sd & 1023;
        float freq = expf(-logf(10000.f) * (float)(d & ~1) / 1024.f);
        float ang = (float)s * freq;
        out[idx] = (d & 1) ? cosf(ang) : sinf(ang);
    }
    if (idx < BDIM * LDIM * DDIM / 8) {
        const float4* src = (const float4*)h;
        uint2* dst = (uint2*)g_hbf;
        float4 a = src[2 * idx], b = src[2 * idx + 1];
        __nv_bfloat162 p0 = __floats2bfloat162_rn(a.x, a.y);
        __nv_bfloat162 p1 = __floats2bfloat162_rn(a.z, a.w);
        __nv_bfloat162 p2 = __floats2bfloat162_rn(b.x, b.y);
        __nv_bfloat162 p3 = __floats2bfloat162_rn(b.z, b.w);
        uint2 o0, o1;
        o0.x = *reinterpret_cast<uint32_t*>(&p0);
        o0.y = *reinterpret_cast<uint32_t*>(&p1);
        o1.x = *reinterpret_cast<uint32_t*>(&p2);
        o1.y = *reinterpret_cast<uint32_t*>(&p3);
        dst[2 * idx] = o0;
        dst[2 * idx + 1] = o1;
    }
    if (idx < NP * KTOT) {
        int c = idx / KTOT, r = idx % KTOT;
        int k = r >> 10, d = r & 1023;
        float v = (c < CH) ? w1[((size_t)c * 1024 + d) * 3 + k] : 0.f;
        g_Wbf[idx] = __float2bfloat16(v);
    }
    if (idx < NP) {
        g_w2p[idx] = (idx < CH) ? w2[idx] : 0.f;
        g_b1p[idx] = (idx < CH) ? b1[idx] : 0.f;
    }
    if (idx < BDIM * LDIM) {
        g_logits[idx] = 0.f;
        // race-free length detect: unique thread at the 1->0 transition writes
        int b = idx >> 11, p = idx & (LDIM - 1);
        if (amask[idx] > 0.5f && (p == LDIM - 1 || amask[idx + 1] <= 0.5f))
            g_len[b] = p + 1;
    }
    if (idx == 0) { out_scalars[0] = 0.f; out_scalars[1] = 0.f; }
}

// ---------------- conv GEMM: bf16 mma.sync, 3-stage, 2 CTA/SM (R10-exact) ----
__global__ __launch_bounds__(256, 2) void k_conv(const float* __restrict__ dummy) {
    extern __shared__ __align__(128) char smem[];
    const uint32_t sb = smem_u32(smem);
    const int tid  = threadIdx.x;
    const int lane = tid & 31;
    const int wid  = tid >> 5;
    const int wm   = wid >> 1;
    const int wn   = wid & 1;
    const int b    = blockIdx.z;
    const int l0   = blockIdx.x * 128;
    const int n0   = blockIdx.y * 128;

    const __nv_bfloat16* hbf = g_hbf;
    const __nv_bfloat16* wbf = g_Wbf;

    auto load_stage = [&](int c, int s) {
        const int k  = c >> 4;
        const int d0 = (c & 15) * 64;
        const int kc = c * 64;
        const uint32_t abase = sb + (unsigned)s * 16384u;
        const uint32_t bbase = sb + 49152u + (unsigned)s * 16384u;
#pragma unroll
        for (int i = 0; i < 4; i++) {
            int idx = tid + i * 256;
            int r = idx >> 3, c8 = idx & 7;
            long grow = (long)b * LDIM + l0 + k + r;
            const __nv_bfloat16* src = hbf + grow * DDIM + d0 + c8 * 8;
            uint32_t dst = abase + (uint32_t)(r * 128 + ((c8 ^ (r & 7)) << 4));
            unsigned nb = (grow < (long)BDIM * LDIM) ? 16u : 0u;
            asm volatile("cp.async.cg.shared.global [%0], [%1], 16, %2;"
                         :: "r"(dst), "l"(src), "r"(nb) : "memory");
        }
#pragma unroll
        for (int i = 0; i < 4; i++) {
            int idx = tid + i * 256;
            int r = idx >> 3, c8 = idx & 7;
            const __nv_bfloat16* src = wbf + (size_t)(n0 + r) * KTOT + kc + c8 * 8;
            uint32_t dst = bbase + (uint32_t)(r * 128 + ((c8 ^ (r & 7)) << 4));
            asm volatile("cp.async.cg.shared.global [%0], [%1], 16;"
                         :: "r"(dst), "l"(src) : "memory");
        }
        asm volatile("cp.async.commit_group;" ::: "memory");
    };

    float acc[2][8][4];
#pragma unroll
    for (int i = 0; i < 2; i++)
#pragma unroll
        for (int j = 0; j < 8; j++)
#pragma unroll
            for (int e = 0; e < 4; e++) acc[i][j][e] = 0.f;

    load_stage(0, 0);
    load_stage(1, 1);

    for (int c = 0; c < NCHUNK; c++) {
        const int s = c % 3;
        if (c + 2 < NCHUNK) {
            load_stage(c + 2, (c + 2) % 3);
            asm volatile("cp.async.wait_group 2;" ::: "memory");
        } else {
            asm volatile("cp.async.wait_group 0;" ::: "memory");
        }
        __syncthreads();

        const uint32_t abase = sb + (unsigned)s * 16384u;
        const uint32_t bbase = sb + 49152u + (unsigned)s * 16384u;

#pragma unroll
        for (int kk = 0; kk < 4; kk++) {
            uint32_t af[2][4];
#pragma unroll
            for (int i = 0; i < 2; i++) {
                int row = wm * 32 + i * 16 + (lane & 15);
                int chk = kk * 2 + (lane >> 4);
                uint32_t addr = abase + (uint32_t)(row * 128 + ((chk ^ (row & 7)) << 4));
                asm volatile(
                    "ldmatrix.sync.aligned.m8n8.x4.shared.b16 {%0,%1,%2,%3}, [%4];"
                    : "=r"(af[i][0]), "=r"(af[i][1]), "=r"(af[i][2]), "=r"(af[i][3])
                    : "r"(addr));
            }
            uint32_t bf[8][2];
#pragma unroll
            for (int jp = 0; jp < 4; jp++) {
                int grp = lane >> 3;
                int nrow = wn * 64 + jp * 16 + (grp >> 1) * 8 + (lane & 7);
                int chk  = kk * 2 + (grp & 1);
                uint32_t addr = bbase + (uint32_t)(nrow * 128 + ((chk ^ (nrow & 7)) << 4));
                asm volatile(
                    "ldmatrix.sync.aligned.m8n8.x4.shared.b16 {%0,%1,%2,%3}, [%4];"
                    : "=r"(bf[jp * 2][0]), "=r"(bf[jp * 2][1]),
                      "=r"(bf[jp * 2 + 1][0]), "=r"(bf[jp * 2 + 1][1])
                    : "r"(addr));
            }
#pragma unroll
            for (int i = 0; i < 2; i++)
#pragma unroll
                for (int j = 0; j < 8; j++) {
                    asm volatile(
                        "mma.sync.aligned.m16n8k16.row.col.f32.bf16.bf16.f32 "
                        "{%0,%1,%2,%3}, {%4,%5,%6,%7}, {%8,%9}, {%0,%1,%2,%3};"
                        : "+f"(acc[i][j][0]), "+f"(acc[i][j][1]),
                          "+f"(acc[i][j][2]), "+f"(acc[i][j][3])
                        : "r"(af[i][0]), "r"(af[i][1]), "r"(af[i][2]), "r"(af[i][3]),
                          "r"(bf[j][0]), "r"(bf[j][1]));
                }
        }
        __syncthreads();
    }

    float* red = (float*)smem;
    if (tid < 128) red[tid] = 0.f;
    __syncthreads();

    const int cbase = n0 + wn * 64 + (lane & 3) * 2;
#pragma unroll
    for (int i = 0; i < 2; i++) {
#pragma unroll
        for (int h = 0; h < 2; h++) {
            float s = 0.f;
#pragma unroll
            for (int j = 0; j < 8; j++) {
                int cc = cbase + j * 8;
                float v0 = acc[i][j][h * 2 + 0];
                float v1 = acc[i][j][h * 2 + 1];
                s += fmaxf(v0 + g_b1p[cc], 0.f) * g_w2p[cc];
                s += fmaxf(v1 + g_b1p[cc + 1], 0.f) * g_w2p[cc + 1];
            }
            int row = wm * 32 + i * 16 + h * 8 + (lane >> 2);
            atomicAdd(&red[row], s);
        }
    }
    __syncthreads();
    if (tid < 128) {
        int l = l0 + tid;
        if (l < LDIM - 2) atomicAdd(&g_logits[b * LDIM + l + 2], red[tid]);
    }
}

// ------- fused: add b2, flag near-zero logits, fp32-recompute them in-block ---
__global__ void k_flagfix(const float* __restrict__ hidden, const float* __restrict__ w1,
                          const float* __restrict__ b1, const float* __restrict__ w2,
                          const float* __restrict__ b2) {
    __shared__ int sh_list[64];
    __shared__ int sh_n;
    __shared__ float sred[256];
    const int tid = threadIdx.x;
    if (tid == 0) sh_n = 0;
    __syncthreads();

    const float b2v = b2[0];
    int idx = blockIdx.x * 256 + tid;
    if (idx < BDIM * (LDIM - 2)) {
        int b = idx / (LDIM - 2), l = idx % (LDIM - 2), p = l + 2;
        float v = g_logits[b * LDIM + p] + b2v;
        g_logits[b * LDIM + p] = v;
        if (fabsf(v) < 0.3f) {
            int i = atomicAdd(&sh_n, 1);
            if (i < 64) sh_list[i] = (b << 16) | p;
        }
    }
    __syncthreads();
    int n = sh_n;
    if (n > 64) n = 64;
    for (int it = 0; it < n; it++) {
        int e = sh_list[it];
        int b = e >> 16, p = e & 0xffff, l = p - 2;
        const float* hb = hidden + ((size_t)b * LDIM + l) * DDIM;
        float s = 0.f;
        for (int c = tid; c < CH; c += 256) {
            float a0 = 0.f, a1 = 0.f, a2 = 0.f;
            const float* wc = w1 + (size_t)c * 3072;
#pragma unroll 4
            for (int d = 0; d < 1024; d++) {
                a0 += hb[d] * wc[d * 3 + 0];
                a1 += hb[1024 + d] * wc[d * 3 + 1];
                a2 += hb[2048 + d] * wc[d * 3 + 2];
            }
            s += fmaxf(a0 + a1 + a2 + b1[c], 0.f) * w2[c];
        }
        sred[tid] = s;
        __syncthreads();
        for (int o = 128; o > 0; o >>= 1) {
            if (tid < o) sred[tid] += sred[tid + o];
            __syncthreads();
        }
        if (tid == 0) g_logits[b * LDIM + p] = sred[0] + b2v;
        __syncthreads();
    }
}

// ---------------- per-batch scan (shuffle-based, uses g_len) -----------------
__global__ void k_scan(float* __restrict__ out_short, float* __restrict__ out_scalars) {
    const int b = blockIdx.x;
    const int tid = threadIdx.x;
    const int lane = tid & 31;
    const int w = tid >> 5;
    __shared__ unsigned char sh_hard[LDIM];
    __shared__ int sh_warp[8];
    __shared__ int sh_count[NSEG];

    const int len = g_len[b];

    for (int p = tid; p < LDIM; p += 256) {
        int bit = (p >= 2 && p < len && g_logits[b * LDIM + p] > 0.f) ? 1 : 0;
        sh_hard[p] = (unsigned char)bit;
    }
    __syncthreads();
    if (tid == 0 && len < LDIM) sh_hard[len - 1] = 1;
    for (int s = tid; s < NSEG; s += 256) sh_count[s] = 0;
    __syncthreads();

    const int base = tid * 8;
    int t = 0;
    for (int q = 0; q < 8; q++) t += sh_hard[base + q];

    int v = t;
#pragma unroll
    for (int o = 1; o < 32; o <<= 1) {
        int u = __shfl_up_sync(0xffffffffu, v, o);
        if (lane >= o) v += u;
    }
    if (lane == 31) sh_warp[w] = v;
    __syncthreads();
    if (w == 0 && lane < 8) {
        int x = sh_warp[lane];
#pragma unroll
        for (int o = 1; o < 8; o <<= 1) {
            int u = __shfl_up_sync(0xffu, x, o);
            if (lane >= o) x += u;
        }
        sh_warp[lane] = x;
    }
    __syncthreads();
    const int incl = v + (w > 0 ? sh_warp[w - 1] : 0);
    const int nb = sh_warp[7];

    int run = incl - t;
    for (int q = 0; q < 8; q++) {
        int p = base + q;
        g_seg[b * LDIM + p] = (unsigned short)run;
        if (p < len && run < NSEG) atomicAdd(&sh_count[run], 1);
        run += sh_hard[p];
    }
    __syncthreads();
    for (int s = tid; s < NSEG; s += 256) g_count[b * NSEG + s] = sh_count[s];
    for (int s = tid; s < NSEG; s += 256) out_short[b * NSEG + s] = (s < nb) ? 1.f : 0.f;
    if (tid == 0) {
        atomicAdd(&out_scalars[0], (float)nb);
        atomicAdd(&out_scalars[1], (float)len);
    }
}

// ------- segment-mean pooling: 64-token chunks, adds partial*inv onto PE -----
__global__ __launch_bounds__(256) void k_pool(const float* __restrict__ hidden,
                                              float* __restrict__ pooled) {
    const int b = blockIdx.y;
    const int c0 = blockIdx.x * 64;
    const int tid = threadIdx.x;
    __shared__ unsigned short sseg[64];
    const int len = g_len[b];
    if (c0 >= len) return;
    if (tid < 64) sseg[tid] = g_seg[b * LDIM + c0 + tid];
    __syncthreads();

    const int d = tid * 4;
    const float* hb = hidden + ((size_t)b * LDIM + c0) * DDIM + d;
    float4 acc = make_float4(0.f, 0.f, 0.f, 0.f);
    int cur = sseg[0];
    const int lim = min(64, len - c0);
    for (int li = 0; li < lim; li++) {
        int s = sseg[li];
        if (s != cur) {
            if (cur < NSEG) {
                float inv = 1.f / ((float)g_count[b * NSEG + cur] + 1e-9f);
                float* pp = pooled + ((size_t)b * NSEG + cur) * DDIM + d;
                atomicAdd(pp + 0, acc.x * inv); atomicAdd(pp + 1, acc.y * inv);
                atomicAdd(pp + 2, acc.z * inv); atomicAdd(pp + 3, acc.w * inv);
            }
            acc = make_float4(0.f, 0.f, 0.f, 0.f);
            cur = s;
        }
        float4 v = *(const float4*)(hb + (size_t)li * DDIM);
        acc.x += v.x; acc.y += v.y; acc.z += v.z; acc.w += v.w;
    }
    if (cur < NSEG) {
        float inv = 1.f / ((float)g_count[b * NSEG + cur] + 1e-9f);
        float* pp = pooled + ((size_t)b * NSEG + cur) * DDIM + d;
        atomicAdd(pp + 0, acc.x * inv); atomicAdd(pp + 1, acc.y * inv);
        atomicAdd(pp + 2, acc.z * inv); atomicAdd(pp + 3, acc.w * inv);
    }
}

// ---------------- launch ----------------
extern "C" void kernel_launch(void* const* d_in, const int* in_sizes, int n_in,
                              void* d_out, int out_size) {
    const float* hidden = (const float*)d_in[0];
    const float* amask  = (const float*)d_in[1];
    const float* w1     = (const float*)d_in[2];
    const float* b1     = (const float*)d_in[3];
    const float* w2     = (const float*)d_in[4];
    const float* b2     = (const float*)d_in[5];
    float* out = (float*)d_out;

    const int pooled_n = BDIM * NSEG * DDIM;
    float* out_scalars = out + (out_size - BDIM * NSEG - 2);
    float* out_short   = out + (out_size - BDIM * NSEG);

    const int smem_bytes = 98304;   // 3 stages x 32KB
    cudaFuncSetAttribute(k_conv, cudaFuncAttributeMaxDynamicSharedMemorySize, smem_bytes);

    k_setup<<<(pooled_n + 255) / 256, 256>>>(hidden, out, out_scalars, w1, b1, w2, amask);
    k_conv<<<dim3(16, 3, BDIM), 256, smem_bytes>>>(nullptr);
    k_flagfix<<<(BDIM * (LDIM - 2) + 255) / 256, 256>>>(hidden, w1, b1, w2, b2);
    k_scan<<<BDIM, 256>>>(out_short, out_scalars);
    k_pool<<<dim3(32, BDIM), 256>>>(hidden, out);
}